// round 9
// baseline (speedup 1.0000x reference)
#include <cuda_runtime.h>
#include <cstdint>

#define BN 64
#define PP 8732
#define CC 81
#define KT 16
#define NR (BN * PP)          // 558848
#define TR 128                // rows per CE tile
#define CEB 4366              // NR / 128 exactly
#define NCH 16
#define CHUNK 546
#define MBLK (BN * NCH)       // 1024 matchA blocks
#define NPOST BN
#define TPB 256
#define PPAD 8960             // 35 * 256
#define THRESH 0.5f
#define VAR0 0.1f
#define VAR1 0.2f

// ---------------- scratch ----------------
__device__ __align__(16) float g_bto[NR];
__device__ __align__(16) int   g_bti[NR];
__device__ __align__(16) float g_lse[NR];
__device__ __align__(16) float g_lm[NR];
__device__ unsigned long long g_best[BN * KT];  // idempotent atomicMax accumulator
__device__ float g_loss_l[BN];
__device__ float g_loss_c[BN];
__device__ int   g_num_pos[BN];
__device__ int   g_rows[BN];    // CE rows done per image (consumer resets)
__device__ int   g_match[BN];   // matchA chunks done per image (consumer resets)
__device__ int   g_done;        // finalize counter (self-resets)

// ---------------- helpers ----------------
static __device__ __forceinline__ unsigned su32(const void* p) {
    return (unsigned)__cvta_generic_to_shared(p);
}
static __device__ __forceinline__ void cp16(unsigned sdst, const void* gsrc) {
    asm volatile("cp.async.cg.shared.global [%0], [%1], 16;" :: "r"(sdst), "l"(gsrc));
}
static __device__ __forceinline__ void cp_wait_all() {
    asm volatile("cp.async.wait_all;" ::: "memory");
}

// ---------------- shared-memory union ----------------
struct SmCE   { float buf[TR * CC]; float part[2][TR]; };
struct SmMatch{ float4 pr[CHUNK]; float4 tt[KT]; float area[KT]; unsigned long long best[KT]; };
struct SmPost {
    float lm[PP];
    int hist[8][256];
    int cum[257];
    int wtot[8], wsuf[8];
    float4 tt[KT];
    int lab[KT]; int fp[KT]; float fov[KT];
    float rf[8], rs[8]; int ri[8];
    float fin[6];
    unsigned prefix; int rem;
    float spos_sh, lsum_sh; int npos_sh, last;
};
union SmU { SmCE ce; SmMatch ma; SmPost po; };

// ---------------- the one kernel ----------------
__global__ __launch_bounds__(TPB, 4) void k_all(const float* __restrict__ conf,
                                                const float* __restrict__ loc,
                                                const float* __restrict__ priors,
                                                const float* __restrict__ targets,
                                                float* __restrict__ out) {
    __shared__ __align__(16) SmU sm;
    const int blk = blockIdx.x;
    const int tid = threadIdx.x;
    const int lane = tid & 31;
    const int w = tid >> 5;

    if (blk < MBLK) {
        // ================= matchA role =================
        const int b = blk >> 4;
        const int c = blk & 15;

        if (tid < KT) {
            const float* tg = targets + (size_t)(b * KT + tid) * 6;
            sm.ma.tt[tid] = make_float4(tg[2], tg[3], tg[4], tg[5]);
            sm.ma.area[tid] = (tg[4] - tg[2]) * (tg[5] - tg[3]);
            sm.ma.best[tid] = 0ull;
        }
        const int p0 = c * CHUNK;
        const int np = (p0 + CHUNK <= PP) ? CHUNK : (PP - p0);
        for (int i = tid; i < np; i += TPB)
            sm.ma.pr[i] = ((const float4*)priors)[p0 + i];
        __syncthreads();

        for (int i = tid; i < np; i += TPB) {
            const float4 pr = sm.ma.pr[i];
            const float parea = (pr.z - pr.x) * (pr.w - pr.y);
            float bestov = -1.0f;
            int besti = 0;
#pragma unroll
            for (int k = 0; k < KT; k++) {
                const float4 t = sm.ma.tt[k];
                float ix = fminf(t.z, pr.z) - fmaxf(t.x, pr.x);
                float iy = fminf(t.w, pr.w) - fmaxf(t.y, pr.y);
                float inter = fmaxf(ix, 0.0f) * fmaxf(iy, 0.0f);
                float ov = inter / (sm.ma.area[k] + parea - inter);
                if (ov > bestov) { bestov = ov; besti = k; }
            }
            g_bto[b * PP + p0 + i] = bestov;
            g_bti[b * PP + p0 + i] = besti;
        }

        for (int k = 0; k < KT; k++) {
            const float4 t = sm.ma.tt[k];
            const float ta = sm.ma.area[k];
            unsigned long long key = 0ull;
            for (int i = tid; i < np; i += TPB) {
                const float4 pr = sm.ma.pr[i];
                const float parea = (pr.z - pr.x) * (pr.w - pr.y);
                float ix = fminf(t.z, pr.z) - fmaxf(t.x, pr.x);
                float iy = fminf(t.w, pr.w) - fmaxf(t.y, pr.y);
                float inter = fmaxf(ix, 0.0f) * fmaxf(iy, 0.0f);
                float ov = inter / (ta + parea - inter);
                unsigned long long kk =
                    ((unsigned long long)__float_as_uint(ov) << 32) |
                    (unsigned long long)(0xFFFFFFFFu - (unsigned)(p0 + i));
                if (kk > key) key = kk;
            }
#pragma unroll
            for (int o = 16; o; o >>= 1) {
                unsigned long long other = __shfl_xor_sync(0xFFFFFFFFu, key, o);
                if (other > key) key = other;
            }
            if (lane == 0)
                atomicMax(&sm.ma.best[k], key);
        }
        __syncthreads();
        if (tid < KT)
            atomicMax(&g_best[b * KT + tid], sm.ma.best[tid]);
        __syncthreads();
        if (tid == 0) {
            __threadfence();
            atomicAdd(&g_match[b], 1);     // publish chunk done
        }
    } else if (blk < MBLK + CEB) {
        // ================= CE role =================
        const int tile = blk - MBLK;
        const int row0 = tile * TR;
        const float* gsrc = conf + (size_t)row0 * CC;
        const unsigned sb = su32(sm.ce.buf);

        for (int i = tid; i < (TR * CC / 4); i += TPB)
            cp16(sb + i * 16, gsrc + i * 4);
        cp_wait_all();
        __syncthreads();

        const int r = tid & (TR - 1);
        const int half = tid >> 7;
        const float* row = sm.ce.buf + r * CC;
        float s = 0.0f;
        if (half == 0) {
#pragma unroll
            for (int c = 0; c < 40; c += 4)
                s += __expf(row[c]) + __expf(row[c + 1]) + __expf(row[c + 2]) + __expf(row[c + 3]);
        } else {
#pragma unroll
            for (int c = 40; c < 80; c += 4)
                s += __expf(row[c]) + __expf(row[c + 1]) + __expf(row[c + 2]) + __expf(row[c + 3]);
            s += __expf(row[80]);
        }
        sm.ce.part[half][r] = s;
        __syncthreads();
        if (tid < TR) {
            const float lse = __logf(sm.ce.part[0][tid] + sm.ce.part[1][tid]);
            g_lse[row0 + tid] = lse;
            g_lm[row0 + tid] = lse - sm.ce.buf[tid * CC];
        }
        __syncthreads();
        if (tid == 0) {
            __threadfence();
            const int i0 = row0 / PP;
            const int i1 = (row0 + TR - 1) / PP;
            if (i0 == i1) {
                atomicAdd(&g_rows[i0], TR);
            } else {
                const int n0 = (i0 + 1) * PP - row0;
                atomicAdd(&g_rows[i0], n0);
                atomicAdd(&g_rows[i1], TR - n0);
            }
        }
    } else {
        // ================= post role (one block per image) =================
        const int b = blk - MBLK - CEB;
        const int bPP = b * PP;

        if (tid == 0) {
            while (*(volatile int*)&g_rows[b] < PP) __nanosleep(256);
            while (*(volatile int*)&g_match[b] < NCH) __nanosleep(256);
            __threadfence();
            g_rows[b] = 0;        // reset for next replay
            g_match[b] = 0;
        }
        __syncthreads();

        if (tid < KT) {
            const float* tg = targets + (size_t)(b * KT + tid) * 6;
            sm.po.lab[tid] = (int)tg[1];
            sm.po.tt[tid] = make_float4(tg[2], tg[3], tg[4], tg[5]);
            unsigned long long key = g_best[b * KT + tid];
            sm.po.fp[tid] = (int)(0xFFFFFFFFu - (unsigned)(key & 0xFFFFFFFFull));
            sm.po.fov[tid] = __uint_as_float((unsigned)(key >> 32));
        }
        for (int i = tid; i < 2048; i += TPB)
            ((int*)sm.po.hist)[i] = 0;
        __syncthreads();

        // phase 1
        float lsum = 0.0f, spos = 0.0f;
        int cnt = 0;
        for (int p = tid; p < PP; p += TPB) {
            float ov = g_bto[bPP + p];
            int ki = g_bti[bPP + p];
#pragma unroll
            for (int k = 0; k < KT; k++)
                if (p == sm.po.fp[k]) { ov = sm.po.fov[k]; ki = k; }
            const int ct = (ov < THRESH) ? 0 : sm.po.lab[ki];
            float lmv = g_lm[bPP + p];
            if (ct > 0) {
                lmv = 0.0f;
                cnt++;
                spos += g_lse[bPP + p] - conf[(size_t)(bPP + p) * CC + ct];
                const float4 pr = ((const float4*)priors)[p];
                const float pcx = 0.5f * (pr.x + pr.z), pcy = 0.5f * (pr.y + pr.w);
                const float pw = pr.z - pr.x, ph = pr.w - pr.y;
                const float4 t = sm.po.tt[ki];
                float g0 = (0.5f * (t.x + t.z) - pcx) / (VAR0 * pw);
                float g1 = (0.5f * (t.y + t.w) - pcy) / (VAR0 * ph);
                float g2 = logf((t.z - t.x) / pw) / VAR1;
                float g3 = logf((t.w - t.y) / ph) / VAR1;
                const float4 ld = ((const float4*)loc)[bPP + p];
                float d, ad;
                d = ld.x - g0; ad = fabsf(d); lsum += (ad < 1.0f) ? 0.5f * d * d : ad - 0.5f;
                d = ld.y - g1; ad = fabsf(d); lsum += (ad < 1.0f) ? 0.5f * d * d : ad - 0.5f;
                d = ld.z - g2; ad = fabsf(d); lsum += (ad < 1.0f) ? 0.5f * d * d : ad - 0.5f;
                d = ld.w - g3; ad = fabsf(d); lsum += (ad < 1.0f) ? 0.5f * d * d : ad - 0.5f;
            }
            sm.po.lm[p] = lmv;
        }
#pragma unroll
        for (int o = 16; o; o >>= 1) {
            lsum += __shfl_xor_sync(0xFFFFFFFFu, lsum, o);
            spos += __shfl_xor_sync(0xFFFFFFFFu, spos, o);
            cnt  += __shfl_xor_sync(0xFFFFFFFFu, cnt, o);
        }
        if (lane == 0) { sm.po.rf[w] = lsum; sm.po.rs[w] = spos; sm.po.ri[w] = cnt; }
        __syncthreads();
        if (tid < 8) {
            float L = sm.po.rf[tid], S = sm.po.rs[tid];
            int C = sm.po.ri[tid];
#pragma unroll
            for (int o = 4; o; o >>= 1) {
                L += __shfl_xor_sync(0xFFu, L, o);
                S += __shfl_xor_sync(0xFFu, S, o);
                C += __shfl_xor_sync(0xFFu, C, o);
            }
            if (tid == 0) { sm.po.lsum_sh = L; sm.po.spos_sh = S; sm.po.npos_sh = C; }
        }
        __syncthreads();

        const int npos = sm.po.npos_sh;
        int k = 3 * npos;
        if (k > PP - 1) k = PP - 1;

        float T = 0.0f;
        if (k > 0) {
            if (tid == 0) { sm.po.prefix = 0u; sm.po.rem = k; }
            __syncthreads();
            for (int shift = 24; shift >= 0; shift -= 8) {
                const unsigned pref = sm.po.prefix;
                const int rem = sm.po.rem;
                const unsigned hm = (shift == 24) ? 0u : (0xFFFFFFFFu << (shift + 8));
                int* hist = sm.po.hist[w];          // private per warp: no atomics
                for (int p = tid; p < PPAD; p += TPB) {
                    const bool v = p < PP;
                    const unsigned bits = v ? __float_as_uint(sm.po.lm[p]) : 0u;
                    const int bin = (bits >> shift) & 255;
                    const bool pred = v && ((bits & hm) == pref);
                    unsigned m = __match_any_sync(0xFFFFFFFFu, bin) &
                                 __ballot_sync(0xFFFFFFFFu, pred);
                    if (pred && lane == (__ffs(m) - 1))
                        hist[bin] += __popc(m);
                }
                __syncthreads();
                // sum 8 copies + suffix scan
                int v = sm.po.hist[0][tid] + sm.po.hist[1][tid] + sm.po.hist[2][tid] + sm.po.hist[3][tid]
                      + sm.po.hist[4][tid] + sm.po.hist[5][tid] + sm.po.hist[6][tid] + sm.po.hist[7][tid];
                int sv = v;
#pragma unroll
                for (int o = 1; o < 32; o <<= 1) {
                    int t2 = __shfl_down_sync(0xFFFFFFFFu, sv, o);
                    if (lane + o < 32) sv += t2;
                }
                if (lane == 0) sm.po.wtot[w] = sv;
                sm.po.cum[tid] = sv;
                __syncthreads();
                if (tid < 8) {
                    int t2 = sm.po.wtot[tid];
#pragma unroll
                    for (int o = 1; o < 8; o <<= 1) {
                        int u = __shfl_down_sync(0xFFu, t2, o);
                        if (tid + o < 8) t2 += u;
                    }
                    sm.po.wsuf[tid] = t2 - sm.po.wtot[tid];
                }
                __syncthreads();
                sm.po.cum[tid] += sm.po.wsuf[w];
                if (tid == 0) sm.po.cum[256] = 0;
                __syncthreads();
                {
                    const int above = sm.po.cum[tid + 1];
                    if (sm.po.cum[tid] >= rem && above < rem) {
                        sm.po.prefix = pref | ((unsigned)tid << shift);
                        sm.po.rem = rem - above;
                    }
#pragma unroll
                    for (int cpy = 0; cpy < 8; cpy++) sm.po.hist[cpy][tid] = 0;
                }
                __syncthreads();
            }
            const unsigned t = sm.po.prefix;
            float sumgt = 0.0f;
            int cntgt = 0;
            for (int p = tid; p < PP; p += TPB) {
                const float lm = sm.po.lm[p];
                if (__float_as_uint(lm) > t) { sumgt += lm; cntgt++; }
            }
#pragma unroll
            for (int o = 16; o; o >>= 1) {
                sumgt += __shfl_xor_sync(0xFFFFFFFFu, sumgt, o);
                cntgt += __shfl_xor_sync(0xFFFFFFFFu, cntgt, o);
            }
            if (lane == 0) { sm.po.rf[w] = sumgt; sm.po.ri[w] = cntgt; }
            __syncthreads();
            if (tid == 0) {
                float S = 0.0f; int C = 0;
                for (int i = 0; i < 8; i++) { S += sm.po.rf[i]; C += sm.po.ri[i]; }
                T = S + (float)(k - C) * __uint_as_float(t);
            }
        }

        if (tid == 0) {
            g_loss_l[b] = sm.po.lsum_sh;
            g_loss_c[b] = sm.po.spos_sh + T;
            g_num_pos[b] = npos;
            __threadfence();
            sm.po.last = (atomicAdd(&g_done, 1) == BN - 1) ? 1 : 0;
        }
        __syncthreads();
        if (sm.po.last) {
            if (tid < 64) {
                float lv = __ldcg(&g_loss_l[tid]);
                float cv = __ldcg(&g_loss_c[tid]);
                float nv = (float)__ldcg(&g_num_pos[tid]);
#pragma unroll
                for (int o = 16; o; o >>= 1) {
                    lv += __shfl_xor_sync(0xFFFFFFFFu, lv, o);
                    cv += __shfl_xor_sync(0xFFFFFFFFu, cv, o);
                    nv += __shfl_xor_sync(0xFFFFFFFFu, nv, o);
                }
                if (lane == 0) { sm.po.fin[w] = lv; sm.po.fin[2 + w] = cv; sm.po.fin[4 + w] = nv; }
            }
            __syncthreads();
            if (tid == 0) {
                const float n = fmaxf(sm.po.fin[4] + sm.po.fin[5], 1.0f);
                out[0] = (sm.po.fin[0] + sm.po.fin[1]) / n;
                out[1] = (sm.po.fin[2] + sm.po.fin[3]) / n;
                g_done = 0;   // self-reset
            }
        }
    }
}

extern "C" void kernel_launch(void* const* d_in, const int* in_sizes, int n_in,
                              void* d_out, int out_size) {
    const float* loc = (const float*)d_in[0];
    const float* conf = (const float*)d_in[1];
    const float* priors = (const float*)d_in[2];
    const float* targets = (const float*)d_in[3];
    float* out = (float*)d_out;

    k_all<<<MBLK + CEB + NPOST, TPB>>>(conf, loc, priors, targets, out);
}

// round 10
// speedup vs baseline: 1.4851x; 1.4851x over previous
#include <cuda_runtime.h>
#include <cstdint>

#define BN 64
#define PP 8732
#define CC 81
#define KT 16
#define NR (BN * PP)          // 558848
#define TR 64                 // rows per CE tile
#define CEB 8732              // NR / 64 exactly
#define NCH 16
#define CHUNK 546
#define MBLK (BN * NCH)       // 1024 matchA blocks (first in grid)
#define THRESH 0.5f
#define VAR0 0.1f
#define VAR1 0.2f
#define TPK 1024
#define PPADK 9216            // 1024*9 uniform bound

// ---------------- scratch ----------------
__device__ __align__(16) float g_bto[NR];
__device__ __align__(16) int   g_bti[NR];
__device__ __align__(16) float g_lse[NR];
__device__ __align__(16) float g_lm[NR];
__device__ unsigned long long g_best[BN * KT];  // idempotent atomicMax accumulator
__device__ float g_loss_l[BN];
__device__ float g_loss_c[BN];
__device__ int   g_num_pos[BN];
__device__ int   g_done;                         // self-resetting

// ---------------- helpers ----------------
static __device__ __forceinline__ unsigned su32(const void* p) {
    return (unsigned)__cvta_generic_to_shared(p);
}
#define MBAR_INIT(a, c) \
    asm volatile("mbarrier.init.shared.b64 [%0], %1;" :: "r"(a), "r"(c) : "memory")
#define MBAR_EXPECT(a, n) \
    asm volatile("mbarrier.arrive.expect_tx.shared.b64 _, [%0], %1;" :: "r"(a), "r"(n) : "memory")
#define BULK_G2S(dst, src, n, mbar) \
    asm volatile("cp.async.bulk.shared::cta.global.mbarrier::complete_tx::bytes [%0], [%1], %2, [%3];" \
                 :: "r"(dst), "l"(src), "r"(n), "r"(mbar) : "memory")
#define MBAR_WAITP(a, par) do {                                                     \
    unsigned _dn = 0;                                                               \
    while (!_dn) {                                                                  \
        asm volatile("{\n\t.reg .pred p;\n\t"                                       \
            "mbarrier.try_wait.parity.acquire.cta.shared::cta.b64 p, [%1], %2, 0x989680;\n\t" \
            "selp.b32 %0, 1, 0, p;\n\t}"                                            \
            : "=r"(_dn) : "r"(a), "r"((unsigned)(par)) : "memory");                 \
    }                                                                               \
} while (0)

// ---------------- smem union ----------------
struct SmCE   { float buf[TR * CC]; float part[2][TR]; };                     // 21248 B
struct SmMatch{ float4 pr[CHUNK]; float4 tt[KT]; float area[KT]; unsigned long long best[KT]; };
union SmU { SmCE ce; SmMatch ma; };

// ---------------- kernel 1: matchA (blocks 0..MBLK-1) + CE (rest, TMA bulk) ----------------
__global__ __launch_bounds__(128) void k_big(const float* __restrict__ conf,
                                             const float* __restrict__ priors,
                                             const float* __restrict__ targets) {
    __shared__ __align__(16) SmU sm;
    __shared__ __align__(8) unsigned long long s_mbar;
    const int blk = blockIdx.x;
    const int tid = threadIdx.x;

    if (blk >= MBLK) {
        // ------- CE role: one TMA bulk per 64-row tile, split-row compute -------
        const int tile = blk - MBLK;
        const int row0 = tile * TR;
        const unsigned mb = su32(&s_mbar);
        if (tid == 0) MBAR_INIT(mb, 1);
        __syncthreads();
        if (tid == 0) {
            MBAR_EXPECT(mb, (unsigned)(TR * CC * 4));
            BULK_G2S(su32(sm.ce.buf), conf + (size_t)row0 * CC, (unsigned)(TR * CC * 4), mb);
        }
        MBAR_WAITP(mb, 0);

        const int r = tid & (TR - 1);
        const int half = tid >> 6;
        const float* row = sm.ce.buf + r * CC;
        float s = 0.0f;
        if (half == 0) {
#pragma unroll
            for (int c = 0; c < 40; c += 4)
                s += __expf(row[c]) + __expf(row[c + 1]) + __expf(row[c + 2]) + __expf(row[c + 3]);
        } else {
#pragma unroll
            for (int c = 40; c < 80; c += 4)
                s += __expf(row[c]) + __expf(row[c + 1]) + __expf(row[c + 2]) + __expf(row[c + 3]);
            s += __expf(row[80]);
        }
        sm.ce.part[half][r] = s;
        __syncthreads();
        if (tid < TR) {
            const float lse = __logf(sm.ce.part[0][tid] + sm.ce.part[1][tid]);
            g_lse[row0 + tid] = lse;
            g_lm[row0 + tid] = lse - sm.ce.buf[tid * CC];
        }
    } else {
        // ------- matchA role (unchanged from R8) -------
        const int b = blk >> 4;
        const int c = blk & 15;

        if (tid < KT) {
            const float* tg = targets + (size_t)(b * KT + tid) * 6;
            sm.ma.tt[tid] = make_float4(tg[2], tg[3], tg[4], tg[5]);
            sm.ma.area[tid] = (tg[4] - tg[2]) * (tg[5] - tg[3]);
            sm.ma.best[tid] = 0ull;
        }
        const int p0 = c * CHUNK;
        const int np = (p0 + CHUNK <= PP) ? CHUNK : (PP - p0);
        for (int i = tid; i < np; i += 128)
            sm.ma.pr[i] = ((const float4*)priors)[p0 + i];
        __syncthreads();

        for (int i = tid; i < np; i += 128) {
            const float4 pr = sm.ma.pr[i];
            const float parea = (pr.z - pr.x) * (pr.w - pr.y);
            float bestov = -1.0f;
            int besti = 0;
#pragma unroll
            for (int k = 0; k < KT; k++) {
                const float4 t = sm.ma.tt[k];
                float ix = fminf(t.z, pr.z) - fmaxf(t.x, pr.x);
                float iy = fminf(t.w, pr.w) - fmaxf(t.y, pr.y);
                float inter = fmaxf(ix, 0.0f) * fmaxf(iy, 0.0f);
                float ov = inter / (sm.ma.area[k] + parea - inter);
                if (ov > bestov) { bestov = ov; besti = k; }
            }
            g_bto[b * PP + p0 + i] = bestov;
            g_bti[b * PP + p0 + i] = besti;
        }

        for (int k = 0; k < KT; k++) {
            const float4 t = sm.ma.tt[k];
            const float ta = sm.ma.area[k];
            unsigned long long key = 0ull;
            for (int i = tid; i < np; i += 128) {
                const float4 pr = sm.ma.pr[i];
                const float parea = (pr.z - pr.x) * (pr.w - pr.y);
                float ix = fminf(t.z, pr.z) - fmaxf(t.x, pr.x);
                float iy = fminf(t.w, pr.w) - fmaxf(t.y, pr.y);
                float inter = fmaxf(ix, 0.0f) * fmaxf(iy, 0.0f);
                float ov = inter / (ta + parea - inter);
                unsigned long long kk =
                    ((unsigned long long)__float_as_uint(ov) << 32) |
                    (unsigned long long)(0xFFFFFFFFu - (unsigned)(p0 + i));
                if (kk > key) key = kk;
            }
#pragma unroll
            for (int o = 16; o; o >>= 1) {
                unsigned long long other = __shfl_xor_sync(0xFFFFFFFFu, key, o);
                if (other > key) key = other;
            }
            if ((tid & 31) == 0)
                atomicMax(&sm.ma.best[k], key);
        }
        __syncthreads();
        if (tid < KT)
            atomicMax(&g_best[b * KT + tid], sm.ma.best[tid]);
    }
}

// ---------------- kernel 2: fused post (identical to R8) ----------------
__global__ __launch_bounds__(TPK) void k_post(const float* __restrict__ conf,
                                              const float* __restrict__ loc,
                                              const float* __restrict__ priors,
                                              const float* __restrict__ targets,
                                              float* __restrict__ out) {
    const int b = blockIdx.x;
    const int tid = threadIdx.x;
    const int lane = tid & 31;
    const int w = tid >> 5;
    const int bPP = b * PP;

    __shared__ __align__(16) float s_lm[PP];
    __shared__ int s_hist[8][256];
    __shared__ int s_cum[257];
    __shared__ int s_wtot[8], s_wsuf[8];
    __shared__ float4 s_tt[KT];
    __shared__ int s_lab[KT];
    __shared__ int s_fp[KT];
    __shared__ float s_fov[KT];
    __shared__ unsigned s_prefix;
    __shared__ int s_rem;
    __shared__ float s_rf[32], s_rs[32];
    __shared__ int s_ri[32];
    __shared__ float s_spos_sh, s_lsum_sh;
    __shared__ int s_npos_sh, s_last;

    if (tid < KT) {
        const float* tg = targets + (size_t)(b * KT + tid) * 6;
        s_lab[tid] = (int)tg[1];
        s_tt[tid] = make_float4(tg[2], tg[3], tg[4], tg[5]);
        unsigned long long key = g_best[b * KT + tid];
        s_fp[tid] = (int)(0xFFFFFFFFu - (unsigned)(key & 0xFFFFFFFFull));
        s_fov[tid] = __uint_as_float((unsigned)(key >> 32));
    }
    for (int i = tid; i < 2048; i += TPK)
        ((int*)s_hist)[i] = 0;
    __syncthreads();

    float lsum = 0.0f, spos = 0.0f;
    int cnt = 0;
    for (int p = tid; p < PP; p += TPK) {
        float ov = g_bto[bPP + p];
        int ki = g_bti[bPP + p];
#pragma unroll
        for (int k = 0; k < KT; k++)
            if (p == s_fp[k]) { ov = s_fov[k]; ki = k; }
        const int ct = (ov < THRESH) ? 0 : s_lab[ki];
        float lmv = g_lm[bPP + p];
        if (ct > 0) {
            lmv = 0.0f;
            cnt++;
            spos += g_lse[bPP + p] - conf[(size_t)(bPP + p) * CC + ct];
            const float4 pr = ((const float4*)priors)[p];
            const float pcx = 0.5f * (pr.x + pr.z), pcy = 0.5f * (pr.y + pr.w);
            const float pw = pr.z - pr.x, ph = pr.w - pr.y;
            const float4 t = s_tt[ki];
            float g0 = (0.5f * (t.x + t.z) - pcx) / (VAR0 * pw);
            float g1 = (0.5f * (t.y + t.w) - pcy) / (VAR0 * ph);
            float g2 = logf((t.z - t.x) / pw) / VAR1;
            float g3 = logf((t.w - t.y) / ph) / VAR1;
            const float4 ld = ((const float4*)loc)[bPP + p];
            float d, ad;
            d = ld.x - g0; ad = fabsf(d); lsum += (ad < 1.0f) ? 0.5f * d * d : ad - 0.5f;
            d = ld.y - g1; ad = fabsf(d); lsum += (ad < 1.0f) ? 0.5f * d * d : ad - 0.5f;
            d = ld.z - g2; ad = fabsf(d); lsum += (ad < 1.0f) ? 0.5f * d * d : ad - 0.5f;
            d = ld.w - g3; ad = fabsf(d); lsum += (ad < 1.0f) ? 0.5f * d * d : ad - 0.5f;
        }
        s_lm[p] = lmv;
    }
#pragma unroll
    for (int o = 16; o; o >>= 1) {
        lsum += __shfl_xor_sync(0xFFFFFFFFu, lsum, o);
        spos += __shfl_xor_sync(0xFFFFFFFFu, spos, o);
        cnt  += __shfl_xor_sync(0xFFFFFFFFu, cnt, o);
    }
    if (lane == 0) { s_rf[w] = lsum; s_rs[w] = spos; s_ri[w] = cnt; }
    __syncthreads();
    if (tid < 32) {
        float L = s_rf[tid], S = s_rs[tid];
        int C = s_ri[tid];
#pragma unroll
        for (int o = 16; o; o >>= 1) {
            L += __shfl_xor_sync(0xFFFFFFFFu, L, o);
            S += __shfl_xor_sync(0xFFFFFFFFu, S, o);
            C += __shfl_xor_sync(0xFFFFFFFFu, C, o);
        }
        if (tid == 0) { s_lsum_sh = L; s_spos_sh = S; s_npos_sh = C; }
    }
    __syncthreads();

    const int npos = s_npos_sh;
    int k = 3 * npos;
    if (k > PP - 1) k = PP - 1;

    float T = 0.0f;
    if (k > 0) {
        if (tid == 0) { s_prefix = 0u; s_rem = k; }
        __syncthreads();
        for (int shift = 24; shift >= 0; shift -= 8) {
            const unsigned pref = s_prefix;
            const int rem = s_rem;
            const unsigned hm = (shift == 24) ? 0u : (0xFFFFFFFFu << (shift + 8));
            int* hist = s_hist[w & 7];
            for (int p = tid; p < PPADK; p += TPK) {
                const bool v = p < PP;
                const unsigned bits = v ? __float_as_uint(s_lm[p]) : 0u;
                const int bin = (bits >> shift) & 255;
                const bool pred = v && ((bits & hm) == pref);
                unsigned m = __match_any_sync(0xFFFFFFFFu, bin) &
                             __ballot_sync(0xFFFFFFFFu, pred);
                if (pred && lane == (__ffs(m) - 1))
                    atomicAdd(&hist[bin], __popc(m));
            }
            __syncthreads();
            int v = 0;
            if (tid < 256) {
                v = s_hist[0][tid] + s_hist[1][tid] + s_hist[2][tid] + s_hist[3][tid]
                  + s_hist[4][tid] + s_hist[5][tid] + s_hist[6][tid] + s_hist[7][tid];
                int sv = v;
#pragma unroll
                for (int o = 1; o < 32; o <<= 1) {
                    int t2 = __shfl_down_sync(0xFFFFFFFFu, sv, o);
                    if (lane + o < 32) sv += t2;
                }
                if (lane == 0) s_wtot[w] = sv;
                s_cum[tid] = sv;
            }
            __syncthreads();
            if (tid < 8) {
                int t2 = s_wtot[tid];
#pragma unroll
                for (int o = 1; o < 8; o <<= 1) {
                    int u = __shfl_down_sync(0xFFu, t2, o);
                    if (tid + o < 8) t2 += u;
                }
                s_wsuf[tid] = t2 - s_wtot[tid];
            }
            __syncthreads();
            if (tid < 256) {
                s_cum[tid] += s_wsuf[w];
                if (tid == 0) s_cum[256] = 0;
            }
            __syncthreads();
            if (tid < 256) {
                const int above = s_cum[tid + 1];
                if (s_cum[tid] >= rem && above < rem) {
                    s_prefix = pref | ((unsigned)tid << shift);
                    s_rem = rem - above;
                }
#pragma unroll
                for (int cpy = 0; cpy < 8; cpy++) s_hist[cpy][tid] = 0;
            }
            __syncthreads();
        }
        const unsigned t = s_prefix;
        float sumgt = 0.0f;
        int cntgt = 0;
        for (int p = tid; p < PP; p += TPK) {
            const float lm = s_lm[p];
            if (__float_as_uint(lm) > t) { sumgt += lm; cntgt++; }
        }
#pragma unroll
        for (int o = 16; o; o >>= 1) {
            sumgt += __shfl_xor_sync(0xFFFFFFFFu, sumgt, o);
            cntgt += __shfl_xor_sync(0xFFFFFFFFu, cntgt, o);
        }
        if (lane == 0) { s_rf[w] = sumgt; s_ri[w] = cntgt; }
        __syncthreads();
        if (tid == 0) {
            float S = 0.0f; int C = 0;
            for (int i = 0; i < 32; i++) { S += s_rf[i]; C += s_ri[i]; }
            T = S + (float)(k - C) * __uint_as_float(t);
        }
    }

    if (tid == 0) {
        g_loss_l[b] = s_lsum_sh;
        g_loss_c[b] = s_spos_sh + T;
        g_num_pos[b] = npos;
        __threadfence();
        s_last = (atomicAdd(&g_done, 1) == BN - 1) ? 1 : 0;
    }
    __syncthreads();
    if (s_last) {
        if (tid < 64) {
            float lv = __ldcg(&g_loss_l[tid]);
            float cv = __ldcg(&g_loss_c[tid]);
            float nv = (float)__ldcg(&g_num_pos[tid]);
#pragma unroll
            for (int o = 16; o; o >>= 1) {
                lv += __shfl_xor_sync(0xFFFFFFFFu, lv, o);
                cv += __shfl_xor_sync(0xFFFFFFFFu, cv, o);
                nv += __shfl_xor_sync(0xFFFFFFFFu, nv, o);
            }
            if (lane == 0) { s_rf[w] = lv; s_rf[w + 2] = cv; s_rf[w + 4] = nv; }
        }
        __syncthreads();
        if (tid == 0) {
            const float n = fmaxf(s_rf[4] + s_rf[5], 1.0f);
            out[0] = (s_rf[0] + s_rf[1]) / n;
            out[1] = (s_rf[2] + s_rf[3]) / n;
            g_done = 0;   // self-reset
        }
    }
}

extern "C" void kernel_launch(void* const* d_in, const int* in_sizes, int n_in,
                              void* d_out, int out_size) {
    const float* loc = (const float*)d_in[0];
    const float* conf = (const float*)d_in[1];
    const float* priors = (const float*)d_in[2];
    const float* targets = (const float*)d_in[3];
    float* out = (float*)d_out;

    k_big<<<MBLK + CEB, 128>>>(conf, priors, targets);
    k_post<<<BN, TPK>>>(conf, loc, priors, targets, out);
}

// round 11
// speedup vs baseline: 1.6144x; 1.0871x over previous
#include <cuda_runtime.h>
#include <cstdint>

#define BN 64
#define PP 8732
#define CC 81
#define KT 16
#define NR (BN * PP)          // 558848
#define TR 128                // rows per CE tile (R3 measured-best)
#define CEB 4366              // NR / 128 exactly
#define NCH 16
#define CHUNK 546
#define MBLK (BN * NCH)       // 1024 matchA blocks (first in grid)
#define THRESH 0.5f
#define VAR0 0.1f
#define VAR1 0.2f
#define TPK 1024
#define PPADK 9216            // 1024*9 uniform bound
#define IMGB (PP * 4)         // 34928 bytes per per-image array (16B aligned)

// ---------------- scratch ----------------
__device__ __align__(16) float g_bto[NR];
__device__ __align__(16) int   g_bti[NR];
__device__ __align__(16) float g_lse[NR];
__device__ __align__(16) float g_lm[NR];
__device__ unsigned long long g_best[BN * KT];  // idempotent atomicMax accumulator
__device__ float g_loss_l[BN];
__device__ float g_loss_c[BN];
__device__ int   g_num_pos[BN];
__device__ int   g_done;                         // self-resetting

// ---------------- helpers ----------------
static __device__ __forceinline__ unsigned su32(const void* p) {
    return (unsigned)__cvta_generic_to_shared(p);
}
#define MBAR_INIT(a, c) \
    asm volatile("mbarrier.init.shared.b64 [%0], %1;" :: "r"(a), "r"(c) : "memory")
#define MBAR_EXPECT(a, n) \
    asm volatile("mbarrier.arrive.expect_tx.shared.b64 _, [%0], %1;" :: "r"(a), "r"(n) : "memory")
#define BULK_G2S(dst, src, n, mbar) \
    asm volatile("cp.async.bulk.shared::cta.global.mbarrier::complete_tx::bytes [%0], [%1], %2, [%3];" \
                 :: "r"(dst), "l"(src), "r"(n), "r"(mbar) : "memory")
#define MBAR_WAITP(a, par) do {                                                     \
    unsigned _dn = 0;                                                               \
    while (!_dn) {                                                                  \
        asm volatile("{\n\t.reg .pred p;\n\t"                                       \
            "mbarrier.try_wait.parity.acquire.cta.shared::cta.b64 p, [%1], %2, 0x989680;\n\t" \
            "selp.b32 %0, 1, 0, p;\n\t}"                                            \
            : "=r"(_dn) : "r"(a), "r"((unsigned)(par)) : "memory");                 \
    }                                                                               \
} while (0)

// ---------------- smem union for k_big ----------------
struct SmCE   { float buf[TR * CC]; };                                         // 41472 B
struct SmMatch{ float4 pr[CHUNK]; float4 tt[KT]; float area[KT]; unsigned long long best[KT]; };
union SmU { SmCE ce; SmMatch ma; };

// ---------------- kernel 1: matchA + CE (R3 config: 128-row TMA tiles, thread-per-row) ----------------
__global__ __launch_bounds__(128) void k_big(const float* __restrict__ conf,
                                             const float* __restrict__ priors,
                                             const float* __restrict__ targets) {
    __shared__ __align__(16) SmU sm;
    __shared__ __align__(8) unsigned long long s_mbar;
    const int blk = blockIdx.x;
    const int tid = threadIdx.x;

    if (blk >= MBLK) {
        // ------- CE role -------
        const int tile = blk - MBLK;
        const int row0 = tile * TR;
        const unsigned mb = su32(&s_mbar);
        if (tid == 0) MBAR_INIT(mb, 1);
        __syncthreads();
        if (tid == 0) {
            MBAR_EXPECT(mb, (unsigned)(TR * CC * 4));
            BULK_G2S(su32(sm.ce.buf), conf + (size_t)row0 * CC, (unsigned)(TR * CC * 4), mb);
        }
        MBAR_WAITP(mb, 0);

        const float* row = sm.ce.buf + tid * CC;
        float s0 = 0.0f, s1 = 0.0f, s2 = 0.0f, s3 = 0.0f;
#pragma unroll 5
        for (int i = 0; i + 3 < CC; i += 4) {
            s0 += __expf(row[i]);
            s1 += __expf(row[i + 1]);
            s2 += __expf(row[i + 2]);
            s3 += __expf(row[i + 3]);
        }
        s0 += __expf(row[CC - 1]);
        const float lse = __logf((s0 + s1) + (s2 + s3));
        g_lse[row0 + tid] = lse;
        g_lm[row0 + tid] = lse - row[0];
    } else {
        // ------- matchA role -------
        const int b = blk >> 4;
        const int c = blk & 15;

        if (tid < KT) {
            const float* tg = targets + (size_t)(b * KT + tid) * 6;
            sm.ma.tt[tid] = make_float4(tg[2], tg[3], tg[4], tg[5]);
            sm.ma.area[tid] = (tg[4] - tg[2]) * (tg[5] - tg[3]);
            sm.ma.best[tid] = 0ull;
        }
        const int p0 = c * CHUNK;
        const int np = (p0 + CHUNK <= PP) ? CHUNK : (PP - p0);
        for (int i = tid; i < np; i += 128)
            sm.ma.pr[i] = ((const float4*)priors)[p0 + i];
        __syncthreads();

        for (int i = tid; i < np; i += 128) {
            const float4 pr = sm.ma.pr[i];
            const float parea = (pr.z - pr.x) * (pr.w - pr.y);
            float bestov = -1.0f;
            int besti = 0;
#pragma unroll
            for (int k = 0; k < KT; k++) {
                const float4 t = sm.ma.tt[k];
                float ix = fminf(t.z, pr.z) - fmaxf(t.x, pr.x);
                float iy = fminf(t.w, pr.w) - fmaxf(t.y, pr.y);
                float inter = fmaxf(ix, 0.0f) * fmaxf(iy, 0.0f);
                float ov = inter / (sm.ma.area[k] + parea - inter);
                if (ov > bestov) { bestov = ov; besti = k; }
            }
            g_bto[b * PP + p0 + i] = bestov;
            g_bti[b * PP + p0 + i] = besti;
        }

        for (int k = 0; k < KT; k++) {
            const float4 t = sm.ma.tt[k];
            const float ta = sm.ma.area[k];
            unsigned long long key = 0ull;
            for (int i = tid; i < np; i += 128) {
                const float4 pr = sm.ma.pr[i];
                const float parea = (pr.z - pr.x) * (pr.w - pr.y);
                float ix = fminf(t.z, pr.z) - fmaxf(t.x, pr.x);
                float iy = fminf(t.w, pr.w) - fmaxf(t.y, pr.y);
                float inter = fmaxf(ix, 0.0f) * fmaxf(iy, 0.0f);
                float ov = inter / (ta + parea - inter);
                unsigned long long kk =
                    ((unsigned long long)__float_as_uint(ov) << 32) |
                    (unsigned long long)(0xFFFFFFFFu - (unsigned)(p0 + i));
                if (kk > key) key = kk;
            }
#pragma unroll
            for (int o = 16; o; o >>= 1) {
                unsigned long long other = __shfl_xor_sync(0xFFFFFFFFu, key, o);
                if (other > key) key = other;
            }
            if ((tid & 31) == 0)
                atomicMax(&sm.ma.best[k], key);
        }
        __syncthreads();
        if (tid < KT)
            atomicMax(&g_best[b * KT + tid], sm.ma.best[tid]);
    }
}

// ---------------- kernel 2: smem-resident post ----------------
// dynamic smem: s_bto[PP], s_lm[PP], s_bti[PP]  (3 * 34928 B)
extern __shared__ float psm[];

__global__ __launch_bounds__(TPK) void k_post(const float* __restrict__ conf,
                                              const float* __restrict__ loc,
                                              const float* __restrict__ priors,
                                              const float* __restrict__ targets,
                                              float* __restrict__ out) {
    const int b = blockIdx.x;
    const int tid = threadIdx.x;
    const int lane = tid & 31;
    const int w = tid >> 5;
    const int bPP = b * PP;

    float* s_bto = psm;
    float* s_lm  = psm + PP;
    int*   s_bti = (int*)(psm + 2 * PP);

    __shared__ int s_hist[8][256];
    __shared__ int s_cum[257];
    __shared__ int s_wtot[8], s_wsuf[8];
    __shared__ float4 s_tt[KT];
    __shared__ int s_lab[KT];
    __shared__ unsigned s_prefix;
    __shared__ int s_rem;
    __shared__ float s_rf[32], s_rs[32];
    __shared__ int s_ri[32];
    __shared__ float s_spos_sh, s_lsum_sh;
    __shared__ int s_npos_sh, s_last;
    __shared__ __align__(8) unsigned long long s_mbar;

    const unsigned mb = su32(&s_mbar);
    if (tid == 0) {
        MBAR_INIT(mb, 1);
        MBAR_EXPECT(mb, 3u * IMGB);
        BULK_G2S(su32(s_bto), g_bto + bPP, (unsigned)IMGB, mb);
        BULK_G2S(su32(s_lm),  g_lm  + bPP, (unsigned)IMGB, mb);
        BULK_G2S(su32(s_bti), g_bti + bPP, (unsigned)IMGB, mb);
    }
    if (tid < KT) {
        const float* tg = targets + (size_t)(b * KT + tid) * 6;
        s_lab[tid] = (int)tg[1];
        s_tt[tid] = make_float4(tg[2], tg[3], tg[4], tg[5]);
    }
    for (int i = tid; i < 2048; i += TPK)
        ((int*)s_hist)[i] = 0;
    __syncthreads();
    MBAR_WAITP(mb, 0);

    // sequential force-assign (last write wins) directly in THIS block's smem copy
    if (tid == 0) {
        for (int k = 0; k < KT; k++) {
            unsigned long long key = g_best[b * KT + k];
            const int p = (int)(0xFFFFFFFFu - (unsigned)(key & 0xFFFFFFFFull));
            s_bto[p] = __uint_as_float((unsigned)(key >> 32));
            s_bti[p] = k;
        }
    }
    __syncthreads();

    // phase 1: conf_t + smooth-L1 + pos-CE + lm patch (all index math from smem)
    float lsum = 0.0f, spos = 0.0f;
    int cnt = 0;
    for (int p = tid; p < PP; p += TPK) {
        const float ov = s_bto[p];
        const int ki = s_bti[p];
        const int ct = (ov < THRESH) ? 0 : s_lab[ki];
        if (ct > 0) {
            s_lm[p] = 0.0f;
            cnt++;
            spos += g_lse[bPP + p] - conf[(size_t)(bPP + p) * CC + ct];
            const float4 pr = ((const float4*)priors)[p];
            const float pcx = 0.5f * (pr.x + pr.z), pcy = 0.5f * (pr.y + pr.w);
            const float pw = pr.z - pr.x, ph = pr.w - pr.y;
            const float4 t = s_tt[ki];
            float g0 = (0.5f * (t.x + t.z) - pcx) / (VAR0 * pw);
            float g1 = (0.5f * (t.y + t.w) - pcy) / (VAR0 * ph);
            float g2 = logf((t.z - t.x) / pw) / VAR1;
            float g3 = logf((t.w - t.y) / ph) / VAR1;
            const float4 ld = ((const float4*)loc)[bPP + p];
            float d, ad;
            d = ld.x - g0; ad = fabsf(d); lsum += (ad < 1.0f) ? 0.5f * d * d : ad - 0.5f;
            d = ld.y - g1; ad = fabsf(d); lsum += (ad < 1.0f) ? 0.5f * d * d : ad - 0.5f;
            d = ld.z - g2; ad = fabsf(d); lsum += (ad < 1.0f) ? 0.5f * d * d : ad - 0.5f;
            d = ld.w - g3; ad = fabsf(d); lsum += (ad < 1.0f) ? 0.5f * d * d : ad - 0.5f;
        }
    }
#pragma unroll
    for (int o = 16; o; o >>= 1) {
        lsum += __shfl_xor_sync(0xFFFFFFFFu, lsum, o);
        spos += __shfl_xor_sync(0xFFFFFFFFu, spos, o);
        cnt  += __shfl_xor_sync(0xFFFFFFFFu, cnt, o);
    }
    if (lane == 0) { s_rf[w] = lsum; s_rs[w] = spos; s_ri[w] = cnt; }
    __syncthreads();
    if (tid < 32) {
        float L = s_rf[tid], S = s_rs[tid];
        int C = s_ri[tid];
#pragma unroll
        for (int o = 16; o; o >>= 1) {
            L += __shfl_xor_sync(0xFFFFFFFFu, L, o);
            S += __shfl_xor_sync(0xFFFFFFFFu, S, o);
            C += __shfl_xor_sync(0xFFFFFFFFu, C, o);
        }
        if (tid == 0) { s_lsum_sh = L; s_spos_sh = S; s_npos_sh = C; }
    }
    __syncthreads();

    const int npos = s_npos_sh;
    int k = 3 * npos;
    if (k > PP - 1) k = PP - 1;

    float T = 0.0f;
    if (k > 0) {
        if (tid == 0) { s_prefix = 0u; s_rem = k; }
        __syncthreads();
        for (int shift = 24; shift >= 0; shift -= 8) {
            const unsigned pref = s_prefix;
            const int rem = s_rem;
            const unsigned hm = (shift == 24) ? 0u : (0xFFFFFFFFu << (shift + 8));
            int* hist = s_hist[w & 7];
            for (int p = tid; p < PPADK; p += TPK) {
                const bool v = p < PP;
                const unsigned bits = v ? __float_as_uint(s_lm[p]) : 0u;
                const int bin = (bits >> shift) & 255;
                const bool pred = v && ((bits & hm) == pref);
                unsigned m = __match_any_sync(0xFFFFFFFFu, bin) &
                             __ballot_sync(0xFFFFFFFFu, pred);
                if (pred && lane == (__ffs(m) - 1))
                    atomicAdd(&hist[bin], __popc(m));
            }
            __syncthreads();
            int v = 0;
            if (tid < 256) {
                v = s_hist[0][tid] + s_hist[1][tid] + s_hist[2][tid] + s_hist[3][tid]
                  + s_hist[4][tid] + s_hist[5][tid] + s_hist[6][tid] + s_hist[7][tid];
                int sv = v;
#pragma unroll
                for (int o = 1; o < 32; o <<= 1) {
                    int t2 = __shfl_down_sync(0xFFFFFFFFu, sv, o);
                    if (lane + o < 32) sv += t2;
                }
                if (lane == 0) s_wtot[w] = sv;
                s_cum[tid] = sv;
            }
            __syncthreads();
            if (tid < 8) {
                int t2 = s_wtot[tid];
#pragma unroll
                for (int o = 1; o < 8; o <<= 1) {
                    int u = __shfl_down_sync(0xFFu, t2, o);
                    if (tid + o < 8) t2 += u;
                }
                s_wsuf[tid] = t2 - s_wtot[tid];
            }
            __syncthreads();
            if (tid < 256) {
                s_cum[tid] += s_wsuf[w];
                if (tid == 0) s_cum[256] = 0;
            }
            __syncthreads();
            if (tid < 256) {
                const int above = s_cum[tid + 1];
                if (s_cum[tid] >= rem && above < rem) {
                    s_prefix = pref | ((unsigned)tid << shift);
                    s_rem = rem - above;
                }
#pragma unroll
                for (int cpy = 0; cpy < 8; cpy++) s_hist[cpy][tid] = 0;
            }
            __syncthreads();
        }
        const unsigned t = s_prefix;
        float sumgt = 0.0f;
        int cntgt = 0;
        for (int p = tid; p < PP; p += TPK) {
            const float lm = s_lm[p];
            if (__float_as_uint(lm) > t) { sumgt += lm; cntgt++; }
        }
#pragma unroll
        for (int o = 16; o; o >>= 1) {
            sumgt += __shfl_xor_sync(0xFFFFFFFFu, sumgt, o);
            cntgt += __shfl_xor_sync(0xFFFFFFFFu, cntgt, o);
        }
        if (lane == 0) { s_rf[w] = sumgt; s_ri[w] = cntgt; }
        __syncthreads();
        if (tid == 0) {
            float S = 0.0f; int C = 0;
            for (int i = 0; i < 32; i++) { S += s_rf[i]; C += s_ri[i]; }
            T = S + (float)(k - C) * __uint_as_float(t);
        }
    }

    if (tid == 0) {
        g_loss_l[b] = s_lsum_sh;
        g_loss_c[b] = s_spos_sh + T;
        g_num_pos[b] = npos;
        __threadfence();
        s_last = (atomicAdd(&g_done, 1) == BN - 1) ? 1 : 0;
    }
    __syncthreads();
    if (s_last) {
        if (tid < 64) {
            float lv = __ldcg(&g_loss_l[tid]);
            float cv = __ldcg(&g_loss_c[tid]);
            float nv = (float)__ldcg(&g_num_pos[tid]);
#pragma unroll
            for (int o = 16; o; o >>= 1) {
                lv += __shfl_xor_sync(0xFFFFFFFFu, lv, o);
                cv += __shfl_xor_sync(0xFFFFFFFFu, cv, o);
                nv += __shfl_xor_sync(0xFFFFFFFFu, nv, o);
            }
            if (lane == 0) { s_rf[w] = lv; s_rf[w + 2] = cv; s_rf[w + 4] = nv; }
        }
        __syncthreads();
        if (tid == 0) {
            const float n = fmaxf(s_rf[4] + s_rf[5], 1.0f);
            out[0] = (s_rf[0] + s_rf[1]) / n;
            out[1] = (s_rf[2] + s_rf[3]) / n;
            g_done = 0;   // self-reset
        }
    }
}

extern "C" void kernel_launch(void* const* d_in, const int* in_sizes, int n_in,
                              void* d_out, int out_size) {
    const float* loc = (const float*)d_in[0];
    const float* conf = (const float*)d_in[1];
    const float* priors = (const float*)d_in[2];
    const float* targets = (const float*)d_in[3];
    float* out = (float*)d_out;

    const int post_dyn = 3 * IMGB;   // 104784 B
    cudaFuncSetAttribute(k_post, cudaFuncAttributeMaxDynamicSharedMemorySize, post_dyn);

    k_big<<<MBLK + CEB, 128>>>(conf, priors, targets);
    k_post<<<BN, TPK, post_dyn>>>(conf, loc, priors, targets, out);
}

// round 12
// speedup vs baseline: 1.9110x; 1.1837x over previous
#include <cuda_runtime.h>
#include <cstdint>

#define BN 64
#define PP 8732
#define CC 81
#define KT 16
#define NR (BN * PP)          // 558848
#define TR 128                // rows per CE tile
#define CEB 4366              // NR / 128 exactly
#define NCH 16
#define CHUNK 546
#define MBLK (BN * NCH)       // 1024 matchA blocks (first in grid)
#define THRESH 0.5f
#define VAR0 0.1f
#define VAR1 0.2f
#define TPK 1024
#define PPADK 9216            // 1024*9 uniform bound (phase-1 collective loop)
#define IMGB (PP * 4)         // 34928 bytes per per-image array (16B aligned)
#define NBIN 8192

// ---------------- scratch ----------------
__device__ __align__(16) float g_bto[NR];
__device__ __align__(16) int   g_bti[NR];
__device__ __align__(16) float g_lm[NR];
__device__ unsigned long long g_best[BN * KT];  // idempotent atomicMax accumulator
__device__ float g_loss_l[BN];
__device__ float g_loss_c[BN];
__device__ int   g_num_pos[BN];
__device__ int   g_done;                         // self-resetting

// ---------------- helpers ----------------
static __device__ __forceinline__ unsigned su32(const void* p) {
    return (unsigned)__cvta_generic_to_shared(p);
}
#define MBAR_INIT(a, c) \
    asm volatile("mbarrier.init.shared.b64 [%0], %1;" :: "r"(a), "r"(c) : "memory")
#define MBAR_EXPECT(a, n) \
    asm volatile("mbarrier.arrive.expect_tx.shared.b64 _, [%0], %1;" :: "r"(a), "r"(n) : "memory")
#define BULK_G2S(dst, src, n, mbar) \
    asm volatile("cp.async.bulk.shared::cta.global.mbarrier::complete_tx::bytes [%0], [%1], %2, [%3];" \
                 :: "r"(dst), "l"(src), "r"(n), "r"(mbar) : "memory")
#define MBAR_WAITP(a, par) do {                                                     \
    unsigned _dn = 0;                                                               \
    while (!_dn) {                                                                  \
        asm volatile("{\n\t.reg .pred p;\n\t"                                       \
            "mbarrier.try_wait.parity.acquire.cta.shared::cta.b64 p, [%1], %2, 0x989680;\n\t" \
            "selp.b32 %0, 1, 0, p;\n\t}"                                            \
            : "=r"(_dn) : "r"(a), "r"((unsigned)(par)) : "memory");                 \
    }                                                                               \
} while (0)

static __device__ __forceinline__ int warp_suffix_incl(int v, int lane) {
#pragma unroll
    for (int o = 1; o < 32; o <<= 1) {
        int t = __shfl_down_sync(0xFFFFFFFFu, v, o);
        if (lane + o < 32) v += t;
    }
    return v;
}

// ---------------- smem union for k_big ----------------
struct SmCE   { float buf[TR * CC]; };                                         // 41472 B
struct SmMatch{ float4 pr[CHUNK]; float4 tt[KT]; float area[KT]; unsigned long long best[KT]; };
union SmU { SmCE ce; SmMatch ma; };

// ---------------- kernel 1: matchA + CE (128-row TMA tiles, thread-per-row) ----------------
__global__ __launch_bounds__(128) void k_big(const float* __restrict__ conf,
                                             const float* __restrict__ priors,
                                             const float* __restrict__ targets) {
    __shared__ __align__(16) SmU sm;
    __shared__ __align__(8) unsigned long long s_mbar;
    const int blk = blockIdx.x;
    const int tid = threadIdx.x;

    if (blk >= MBLK) {
        // ------- CE role -------
        const int tile = blk - MBLK;
        const int row0 = tile * TR;
        const unsigned mb = su32(&s_mbar);
        if (tid == 0) MBAR_INIT(mb, 1);
        __syncthreads();
        if (tid == 0) {
            MBAR_EXPECT(mb, (unsigned)(TR * CC * 4));
            BULK_G2S(su32(sm.ce.buf), conf + (size_t)row0 * CC, (unsigned)(TR * CC * 4), mb);
        }
        MBAR_WAITP(mb, 0);

        const float* row = sm.ce.buf + tid * CC;
        float s0 = 0.0f, s1 = 0.0f, s2 = 0.0f, s3 = 0.0f;
#pragma unroll 5
        for (int i = 0; i + 3 < CC; i += 4) {
            s0 += __expf(row[i]);
            s1 += __expf(row[i + 1]);
            s2 += __expf(row[i + 2]);
            s3 += __expf(row[i + 3]);
        }
        s0 += __expf(row[CC - 1]);
        const float lse = __logf((s0 + s1) + (s2 + s3));
        g_lm[row0 + tid] = lse - row[0];
    } else {
        // ------- matchA role -------
        const int b = blk >> 4;
        const int c = blk & 15;

        if (tid < KT) {
            const float* tg = targets + (size_t)(b * KT + tid) * 6;
            sm.ma.tt[tid] = make_float4(tg[2], tg[3], tg[4], tg[5]);
            sm.ma.area[tid] = (tg[4] - tg[2]) * (tg[5] - tg[3]);
            sm.ma.best[tid] = 0ull;
        }
        const int p0 = c * CHUNK;
        const int np = (p0 + CHUNK <= PP) ? CHUNK : (PP - p0);
        for (int i = tid; i < np; i += 128)
            sm.ma.pr[i] = ((const float4*)priors)[p0 + i];
        __syncthreads();

        for (int i = tid; i < np; i += 128) {
            const float4 pr = sm.ma.pr[i];
            const float parea = (pr.z - pr.x) * (pr.w - pr.y);
            float bestov = -1.0f;
            int besti = 0;
#pragma unroll
            for (int k = 0; k < KT; k++) {
                const float4 t = sm.ma.tt[k];
                float ix = fminf(t.z, pr.z) - fmaxf(t.x, pr.x);
                float iy = fminf(t.w, pr.w) - fmaxf(t.y, pr.y);
                float inter = fmaxf(ix, 0.0f) * fmaxf(iy, 0.0f);
                float ov = inter / (sm.ma.area[k] + parea - inter);
                if (ov > bestov) { bestov = ov; besti = k; }
            }
            g_bto[b * PP + p0 + i] = bestov;
            g_bti[b * PP + p0 + i] = besti;
        }

        for (int k = 0; k < KT; k++) {
            const float4 t = sm.ma.tt[k];
            const float ta = sm.ma.area[k];
            unsigned long long key = 0ull;
            for (int i = tid; i < np; i += 128) {
                const float4 pr = sm.ma.pr[i];
                const float parea = (pr.z - pr.x) * (pr.w - pr.y);
                float ix = fminf(t.z, pr.z) - fmaxf(t.x, pr.x);
                float iy = fminf(t.w, pr.w) - fmaxf(t.y, pr.y);
                float inter = fmaxf(ix, 0.0f) * fmaxf(iy, 0.0f);
                float ov = inter / (ta + parea - inter);
                unsigned long long kk =
                    ((unsigned long long)__float_as_uint(ov) << 32) |
                    (unsigned long long)(0xFFFFFFFFu - (unsigned)(p0 + i));
                if (kk > key) key = kk;
            }
#pragma unroll
            for (int o = 16; o; o >>= 1) {
                unsigned long long other = __shfl_xor_sync(0xFFFFFFFFu, key, o);
                if (other > key) key = other;
            }
            if ((tid & 31) == 0)
                atomicMax(&sm.ma.best[k], key);
        }
        __syncthreads();
        if (tid < KT)
            atomicMax(&g_best[b * KT + tid], sm.ma.best[tid]);
    }
}

// ---------------- kernel 2: smem-resident post with single-histogram select ----------------
// dyn smem: s_bto[PP] | s_lm[PP] | s_bti[PP] | s_hist[8192]   (137552 B)
extern __shared__ float psm[];

__global__ __launch_bounds__(TPK) void k_post(const float* __restrict__ conf,
                                              const float* __restrict__ loc,
                                              const float* __restrict__ priors,
                                              const float* __restrict__ targets,
                                              float* __restrict__ out) {
    const int b = blockIdx.x;
    const int tid = threadIdx.x;
    const int lane = tid & 31;
    const int w = tid >> 5;
    const int bPP = b * PP;

    float* s_bto  = psm;                       // reused as list1 after phase 1
    float* s_lm   = psm + PP;
    int*   s_bti  = (int*)(psm + 2 * PP);      // reused as list2 (float bits) after phase 1
    int*   s_hist = (int*)(psm + 3 * PP);
    float* s_list1 = s_bto;
    float* s_list2 = (float*)s_bti;

    __shared__ int s_wtot[32], s_wsuf[32];
    __shared__ float4 s_tt[KT];
    __shared__ int s_lab[KT];
    __shared__ float s_rf[32], s_rs[32];
    __shared__ int s_ri[32];
    __shared__ float s_spos_sh, s_lsum_sh, s_T, s_val;
    __shared__ int s_npos_sh, s_last;
    __shared__ int s_B, s_rem, s_B2, s_rem2, s_B3, s_rem3;
    __shared__ int s_cnt1, s_cnt2;
    __shared__ __align__(8) unsigned long long s_mbar;

    const unsigned mb = su32(&s_mbar);
    if (tid == 0) {
        MBAR_INIT(mb, 1);
        MBAR_EXPECT(mb, 3u * IMGB);
        BULK_G2S(su32(s_bto), g_bto + bPP, (unsigned)IMGB, mb);
        BULK_G2S(su32(s_lm),  g_lm  + bPP, (unsigned)IMGB, mb);
        BULK_G2S(su32(s_bti), g_bti + bPP, (unsigned)IMGB, mb);
        s_T = 0.0f; s_cnt1 = 0; s_cnt2 = 0;
    }
    if (tid < KT) {
        const float* tg = targets + (size_t)(b * KT + tid) * 6;
        s_lab[tid] = (int)tg[1];
        s_tt[tid] = make_float4(tg[2], tg[3], tg[4], tg[5]);
    }
#pragma unroll
    for (int i = 0; i < NBIN / TPK; i++)
        s_hist[tid + i * TPK] = 0;
    __syncthreads();
    MBAR_WAITP(mb, 0);

    // sequential force-assign (last write wins) in this block's smem copy
    if (tid == 0) {
        for (int k = 0; k < KT; k++) {
            unsigned long long key = g_best[b * KT + k];
            const int p = (int)(0xFFFFFFFFu - (unsigned)(key & 0xFFFFFFFFull));
            s_bto[p] = __uint_as_float((unsigned)(key >> 32));
            s_bti[p] = k;
        }
    }
    __syncthreads();

    // ---- phase 1: conf_t + smooth-L1 + pos-CE + lm finalize + 13-bit histogram ----
    float lsum = 0.0f, spos = 0.0f;
    int cnt = 0;
    for (int p = tid; p < PPADK; p += TPK) {
        const bool valid = p < PP;
        float lmv = 0.0f;
        if (valid) {
            const float ov = s_bto[p];
            const int ki = s_bti[p];
            const int ct = (ov < THRESH) ? 0 : s_lab[ki];
            lmv = s_lm[p];
            if (ct > 0) {
                cnt++;
                const float* crow = conf + (size_t)(bPP + p) * CC;
                spos += lmv + crow[0] - crow[ct];    // = lse - conf[ct]
                lmv = 0.0f;
                s_lm[p] = 0.0f;
                const float4 pr = ((const float4*)priors)[p];
                const float pcx = 0.5f * (pr.x + pr.z), pcy = 0.5f * (pr.y + pr.w);
                const float pw = pr.z - pr.x, ph = pr.w - pr.y;
                const float4 t = s_tt[ki];
                float g0 = (0.5f * (t.x + t.z) - pcx) / (VAR0 * pw);
                float g1 = (0.5f * (t.y + t.w) - pcy) / (VAR0 * ph);
                float g2 = logf((t.z - t.x) / pw) / VAR1;
                float g3 = logf((t.w - t.y) / ph) / VAR1;
                const float4 ld = ((const float4*)loc)[bPP + p];
                float d, ad;
                d = ld.x - g0; ad = fabsf(d); lsum += (ad < 1.0f) ? 0.5f * d * d : ad - 0.5f;
                d = ld.y - g1; ad = fabsf(d); lsum += (ad < 1.0f) ? 0.5f * d * d : ad - 0.5f;
                d = ld.z - g2; ad = fabsf(d); lsum += (ad < 1.0f) ? 0.5f * d * d : ad - 0.5f;
                d = ld.w - g3; ad = fabsf(d); lsum += (ad < 1.0f) ? 0.5f * d * d : ad - 0.5f;
            }
        }
        // histogram (warp-aggregated)
        const int bin = (int)(__float_as_uint(lmv) >> 19);   // lm >= 0 => 13 bits
        unsigned m = __match_any_sync(0xFFFFFFFFu, bin) &
                     __ballot_sync(0xFFFFFFFFu, valid);
        if (valid && lane == (__ffs(m) - 1))
            atomicAdd(&s_hist[bin], __popc(m));
    }
#pragma unroll
    for (int o = 16; o; o >>= 1) {
        lsum += __shfl_xor_sync(0xFFFFFFFFu, lsum, o);
        spos += __shfl_xor_sync(0xFFFFFFFFu, spos, o);
        cnt  += __shfl_xor_sync(0xFFFFFFFFu, cnt, o);
    }
    if (lane == 0) { s_rf[w] = lsum; s_rs[w] = spos; s_ri[w] = cnt; }
    __syncthreads();
    if (tid < 32) {
        float L = s_rf[tid], S = s_rs[tid];
        int C = s_ri[tid];
#pragma unroll
        for (int o = 16; o; o >>= 1) {
            L += __shfl_xor_sync(0xFFFFFFFFu, L, o);
            S += __shfl_xor_sync(0xFFFFFFFFu, S, o);
            C += __shfl_xor_sync(0xFFFFFFFFu, C, o);
        }
        if (tid == 0) { s_lsum_sh = L; s_spos_sh = S; s_npos_sh = C; }
    }
    __syncthreads();

    const int npos = s_npos_sh;
    int k = 3 * npos;
    if (k > PP - 1) k = PP - 1;

    if (k > 0) {
        // ---- main histogram suffix scan: find boundary bin B, remainder s_rem ----
        int h[8];
        int tot = 0;
        const int base = tid * 8;
#pragma unroll
        for (int j = 0; j < 8; j++) { h[j] = s_hist[base + j]; tot += h[j]; }
        int sv = warp_suffix_incl(tot, lane);
        if (lane == 0) s_wtot[w] = sv;
        __syncthreads();
        if (tid < 32) {
            int t2 = warp_suffix_incl(s_wtot[tid], tid);
            s_wsuf[tid] = t2 - s_wtot[tid];
        }
        __syncthreads();
        int cumAbove = (sv - tot) + s_wsuf[w];   // bins above this thread's range
#pragma unroll
        for (int j = 7; j >= 0; j--) {
            const int c = cumAbove + h[j];
            if (c >= k && cumAbove < k) { s_B = base + j; s_rem = k - cumAbove; }
            cumAbove = c;
        }
        __syncthreads();
        const int B = s_B;

        // ---- pass 2: sum above B, compact bin-B values into list1 ----
        float sum3 = 0.0f;
        for (int p = tid; p < PP; p += TPK) {
            const float lmv = s_lm[p];
            const int bin = (int)(__float_as_uint(lmv) >> 19);
            if (bin > B) sum3 += lmv;
            else if (bin == B) s_list1[atomicAdd(&s_cnt1, 1)] = lmv;
        }
#pragma unroll
        for (int o = 16; o; o >>= 1)
            sum3 += __shfl_xor_sync(0xFFFFFFFFu, sum3, o);
        if (lane == 0) atomicAdd(&s_T, sum3);

        // ---- level A: 10-bit select within list1 ----
        if (tid < 1024) s_hist[tid] = 0;
        __syncthreads();
        const int cnt1 = s_cnt1;
        for (int i = tid; i < cnt1; i += TPK)
            atomicAdd(&s_hist[(__float_as_uint(s_list1[i]) >> 9) & 0x3FF], 1);
        __syncthreads();
        {
            const int totA = s_hist[tid & 1023] * (tid < 1024 ? 1 : 0);
            int svA = warp_suffix_incl(totA, lane);
            if (lane == 0) s_wtot[w] = svA;
            __syncthreads();
            if (tid < 32) {
                int t2 = warp_suffix_incl(s_wtot[tid], tid);
                s_wsuf[tid] = t2 - s_wtot[tid];
            }
            __syncthreads();
            const int cumE = (svA - totA) + s_wsuf[w];
            if (tid < 1024 && cumE + totA >= s_rem && cumE < s_rem) {
                s_B2 = tid;
                s_rem2 = s_rem - cumE;
            }
        }
        __syncthreads();
        const int B2 = s_B2;
        float sumA = 0.0f;
        for (int i = tid; i < cnt1; i += TPK) {
            const float v = s_list1[i];
            const int binA = (int)((__float_as_uint(v) >> 9) & 0x3FF);
            if (binA > B2) sumA += v;
            else if (binA == B2) s_list2[atomicAdd(&s_cnt2, 1)] = v;
        }
#pragma unroll
        for (int o = 16; o; o >>= 1)
            sumA += __shfl_xor_sync(0xFFFFFFFFu, sumA, o);
        if (lane == 0 && sumA != 0.0f) atomicAdd(&s_T, sumA);

        // ---- level B: 9-bit select within list2 ----
        if (tid < 512) s_hist[tid] = 0;
        __syncthreads();
        const int cnt2 = s_cnt2;
        for (int i = tid; i < cnt2; i += TPK)
            atomicAdd(&s_hist[__float_as_uint(s_list2[i]) & 0x1FF], 1);
        __syncthreads();
        {
            const int totB = (tid < 512) ? s_hist[tid] : 0;
            int svB = warp_suffix_incl(totB, lane);
            if (lane == 0) s_wtot[w] = svB;
            __syncthreads();
            if (tid < 32) {
                int t2 = warp_suffix_incl(s_wtot[tid], tid);
                s_wsuf[tid] = t2 - s_wtot[tid];
            }
            __syncthreads();
            const int cumE = (svB - totB) + s_wsuf[w];
            if (tid < 512 && cumE + totB >= s_rem2 && cumE < s_rem2) {
                s_B3 = tid;
                s_rem3 = s_rem2 - cumE;
            }
        }
        __syncthreads();
        const int B3 = s_B3;
        float sumB = 0.0f;
        for (int i = tid; i < cnt2; i += TPK) {
            const float v = s_list2[i];
            if ((int)(__float_as_uint(v) & 0x1FF) > B3) sumB += v;
        }
#pragma unroll
        for (int o = 16; o; o >>= 1)
            sumB += __shfl_xor_sync(0xFFFFFFFFu, sumB, o);
        if (lane == 0 && sumB != 0.0f) atomicAdd(&s_T, sumB);
        if (tid == 0) {
            const unsigned bits = ((unsigned)B << 19) | ((unsigned)B2 << 9) | (unsigned)B3;
            s_T += (float)s_rem3 * __uint_as_float(bits);
        }
        __syncthreads();
    }

    if (tid == 0) {
        g_loss_l[b] = s_lsum_sh;
        g_loss_c[b] = s_spos_sh + s_T;
        g_num_pos[b] = npos;
        __threadfence();
        s_last = (atomicAdd(&g_done, 1) == BN - 1) ? 1 : 0;
    }
    __syncthreads();
    if (s_last) {
        if (tid < 64) {
            float lv = __ldcg(&g_loss_l[tid]);
            float cv = __ldcg(&g_loss_c[tid]);
            float nv = (float)__ldcg(&g_num_pos[tid]);
#pragma unroll
            for (int o = 16; o; o >>= 1) {
                lv += __shfl_xor_sync(0xFFFFFFFFu, lv, o);
                cv += __shfl_xor_sync(0xFFFFFFFFu, cv, o);
                nv += __shfl_xor_sync(0xFFFFFFFFu, nv, o);
            }
            if (lane == 0) { s_rf[w] = lv; s_rf[w + 2] = cv; s_rf[w + 4] = nv; }
        }
        __syncthreads();
        if (tid == 0) {
            const float n = fmaxf(s_rf[4] + s_rf[5], 1.0f);
            out[0] = (s_rf[0] + s_rf[1]) / n;
            out[1] = (s_rf[2] + s_rf[3]) / n;
            g_done = 0;   // self-reset
        }
    }
}

extern "C" void kernel_launch(void* const* d_in, const int* in_sizes, int n_in,
                              void* d_out, int out_size) {
    const float* loc = (const float*)d_in[0];
    const float* conf = (const float*)d_in[1];
    const float* priors = (const float*)d_in[2];
    const float* targets = (const float*)d_in[3];
    float* out = (float*)d_out;

    const int post_dyn = 3 * IMGB + NBIN * 4;   // 137552 B
    cudaFuncSetAttribute(k_post, cudaFuncAttributeMaxDynamicSharedMemorySize, post_dyn);

    k_big<<<MBLK + CEB, 128>>>(conf, priors, targets);
    k_post<<<BN, TPK, post_dyn>>>(conf, loc, priors, targets, out);
}